// round 11
// baseline (speedup 1.0000x reference)
#include <cuda_runtime.h>
#include <cuda_bf16.h>
#include <cstdint>
#include <cstddef>

#define Bn 128
#define Tn 1024
typedef unsigned long long ull;

__device__ float g_xp[(size_t)2 * Tn * Bn * 512];   // [dir][t][b][512row]
__device__ float g_h0[(size_t)Bn * Tn * 256];       // [b][t][dir*128+u]
__device__ float g_hfin[2 * Bn * 128];              // [dir][b][u]

__device__ __forceinline__ void fma2(ull& d, ull a, ull b) {
    asm("fma.rn.f32x2 %0,%1,%2,%0;" : "+l"(d) : "l"(a), "l"(b));
}
__device__ __forceinline__ float hsum2(ull v) {
    float a, b; asm("mov.b64 {%0,%1},%2;" : "=f"(a), "=f"(b) : "l"(v)); return a + b;
}
__device__ __forceinline__ float sigf(float x) { return __fdividef(1.f, 1.f + __expf(-x)); }
__device__ __forceinline__ float tanhfast(float x) {
    return __fdividef(2.f, 1.f + __expf(-2.f * x)) - 1.f;
}
__device__ __forceinline__ unsigned s2u(const void* p) {
    unsigned a;
    asm("{.reg .u64 t; cvta.to.shared.u64 t, %1; cvt.u32.u64 %0, t;}" : "=r"(a) : "l"(p));
    return a;
}
__device__ __forceinline__ void cp8(void* s, const void* g) {
    asm volatile("cp.async.ca.shared.global [%0], [%1], 8;"
                 :: "r"(s2u(s)), "l"(g) : "memory");
}

// ---------------------------------------------------------------------------
// Projection (R9-proven version, unchanged): g_xp = A·W^T + b_ih + b_hh
// Double-buffered cp.async K-chunks. CTA: 64 tok x 128 rows; thread 4x8 f32x2.
// ---------------------------------------------------------------------------
template <int K, int CH, bool GATHER>
__global__ void __launch_bounds__(256) proj_kernel(
    const int* __restrict__ x, const float* __restrict__ src,
    const float* __restrict__ Wf, const float* __restrict__ Wr,
    const float* __restrict__ bif, const float* __restrict__ bhf,
    const float* __restrict__ bir, const float* __restrict__ bhr)
{
    const int dir     = blockIdx.z;
    const int tokBase = blockIdx.x * 64;
    const int rowBase = blockIdx.y * 128;
    const float* __restrict__ W  = dir ? Wr  : Wf;
    const float* __restrict__ bi = dir ? bir : bif;
    const float* __restrict__ bh = dir ? bhr : bhf;

    constexpr int CP  = CH + 2;
    constexpr int CH2 = CH / 2;
    constexpr int NC  = K / CH;
    __shared__ __align__(16) float As[2][64 * CP];
    __shared__ __align__(16) float Ws[2][128 * CP];
    __shared__ int xs[64];

    const int tid = threadIdx.x;
    if (GATHER && tid < 64) xs[tid] = x[tokBase + tid];
    __syncthreads();

    auto pre = [&](int c, int buf) {
        const int kb = c * CH;
        for (int p = tid; p < 64 * CH2; p += 256) {
            int tok = p / CH2, kp = p - tok * CH2;
            const float* g = GATHER ? src + (size_t)xs[tok] * K + kb + 2 * kp
                                    : g_h0 + (size_t)(tokBase + tok) * 256 + kb + 2 * kp;
            cp8(&As[buf][tok * CP + 2 * kp], g);
        }
        for (int p = tid; p < 128 * CH2; p += 256) {
            int r = p / CH2, kp = p - r * CH2;
            cp8(&Ws[buf][r * CP + 2 * kp], W + (size_t)(rowBase + r) * K + kb + 2 * kp);
        }
        asm volatile("cp.async.commit_group;" ::: "memory");
    };

    const int tg = tid & 15;
    const int rg = tid >> 4;

    ull acc[4][8];
#pragma unroll
    for (int i = 0; i < 4; i++)
#pragma unroll
        for (int j = 0; j < 8; j++) acc[i][j] = 0ull;

    pre(0, 0);
    for (int c = 0; c < NC; c++) {
        asm volatile("cp.async.wait_group 0;" ::: "memory");
        __syncthreads();
        if (c + 1 < NC) pre(c + 1, (c + 1) & 1);
        const float* Ab = &As[c & 1][0];
        const float* Wb = &Ws[c & 1][0];
#pragma unroll
        for (int kp = 0; kp < CH2; kp++) {
            ull a[4], w[8];
#pragma unroll
            for (int i = 0; i < 4; i++)
                a[i] = *(const ull*)&Ab[(tg * 4 + i) * CP + 2 * kp];
#pragma unroll
            for (int j = 0; j < 8; j++)
                w[j] = *(const ull*)&Wb[(rg * 8 + j) * CP + 2 * kp];
#pragma unroll
            for (int i = 0; i < 4; i++)
#pragma unroll
                for (int j = 0; j < 8; j++) fma2(acc[i][j], a[i], w[j]);
        }
        __syncthreads();
    }

    float bias[8];
#pragma unroll
    for (int j = 0; j < 8; j++) {
        int r = rowBase + rg * 8 + j;
        bias[j] = bi[r] + bh[r];
    }
#pragma unroll
    for (int i = 0; i < 4; i++) {
        int tok = tokBase + tg * 4 + i;
        int b = tok >> 10, t = tok & 1023;
        float* o = &g_xp[((size_t)(dir * Tn + t) * Bn + b) * 512 + rowBase + rg * 8];
#pragma unroll
        for (int j = 0; j < 8; j++) o[j] = hsum2(acc[i][j]) + bias[j];
    }
}

// ---------------------------------------------------------------------------
// Recurrence: 2-CTA cluster per (dir, 4-batch group), 512 threads, k-split.
// Thread = (row slot r in [0,256), k-half kh): 32 w-pairs in regs,
// 4 batch partial dots -> psm -> 256 elementwise threads finish the cell.
// ALL threads wait on the mbarrier each step (R9-proven handshake semantics).
// ---------------------------------------------------------------------------
template <int LAYER>
__global__ void __launch_bounds__(512, 1) __cluster_dims__(2, 1, 1)
rec_kernel(const float* __restrict__ Whf, const float* __restrict__ Whr)
{
    const int rank = (int)(blockIdx.x & 1);
    const int cid  = (int)(blockIdx.x >> 1);
    const int dir  = cid >> 5;
    const int b0   = (cid & 31) * 4;
    const int u0   = rank * 64;
    const int tid  = threadIdx.x;
    const int kh   = tid >> 8;          // k-half (warp-uniform)
    const int r    = tid & 255;         // row slot = unit + gate*64
    const int unit = r & 63;
    const int gate = r >> 6;
    const int wrow = u0 + unit + (gate << 7);   // gate order i,f,g,o
    const float* __restrict__ Wh = dir ? Whr : Whf;

    __shared__ __align__(16) float hsm[2][4][128];
    __shared__ __align__(16) float psm[2][4][256];
    __shared__ __align__(8)  ull   mbar[1];

    ull wp[32];
    {
        const ull* wrp = (const ull*)(Wh + (size_t)wrow * 128 + kh * 64);
#pragma unroll
        for (int kp = 0; kp < 32; kp++) wp[kp] = wrp[kp];
    }

    ((float*)hsm)[tid] = 0.f;   // zero buffer 0 (512 floats, one per thread)
    const unsigned mb_l = s2u(mbar);
    if (tid == 0)
        asm volatile("mbarrier.init.shared.b64 [%0], 2;" :: "r"(mb_l) : "memory");

    unsigned hs_peer, mb_self, mb_peer;
    {
        const unsigned hl = s2u(&hsm[0][0][0]);
        asm("mapa.shared::cluster.u32 %0, %1, %2;" : "=r"(hs_peer) : "r"(hl), "r"((unsigned)(rank ^ 1)));
        asm("mapa.shared::cluster.u32 %0, %1, %2;" : "=r"(mb_self) : "r"(mb_l), "r"((unsigned)rank));
        asm("mapa.shared::cluster.u32 %0, %1, %2;" : "=r"(mb_peer) : "r"(mb_l), "r"((unsigned)(rank ^ 1)));
    }
    asm volatile("barrier.cluster.arrive.aligned;" ::: "memory");
    asm volatile("barrier.cluster.wait.aligned;"   ::: "memory");

    const int tstep = dir ? -1 : 1;
    int tcur = dir ? (Tn - 1) : 0;

    const int eb = tid >> 6;    // elementwise owner (tid<256): batch
    const int eu = tid & 63;    //                              local unit
    float xpf[4];
    if (tid < 256) {
        const float* xb = g_xp + ((size_t)(dir * Tn + tcur) * Bn + b0 + eb) * 512 + u0 + eu;
#pragma unroll
        for (int g = 0; g < 4; g++) xpf[g] = xb[g << 7];
    }

    float creg = 0.f, hreg = 0.f;
    int buf = 0;

    for (int s = 0; s < Tn; s++) {
        ull a0 = 0, a1 = 0, a2 = 0, a3 = 0;
        const float* hb = &hsm[buf][0][kh * 64];
#pragma unroll
        for (int kq = 0; kq < 16; kq++) {
            ulonglong2 v0 = *(const ulonglong2*)&hb[4 * kq];
            ulonglong2 v1 = *(const ulonglong2*)&hb[128 + 4 * kq];
            ulonglong2 v2 = *(const ulonglong2*)&hb[256 + 4 * kq];
            ulonglong2 v3 = *(const ulonglong2*)&hb[384 + 4 * kq];
            fma2(a0, wp[2 * kq], v0.x); fma2(a0, wp[2 * kq + 1], v0.y);
            fma2(a1, wp[2 * kq], v1.x); fma2(a1, wp[2 * kq + 1], v1.y);
            fma2(a2, wp[2 * kq], v2.x); fma2(a2, wp[2 * kq + 1], v2.y);
            fma2(a3, wp[2 * kq], v3.x); fma2(a3, wp[2 * kq + 1], v3.y);
        }
        psm[kh][0][r] = hsum2(a0);
        psm[kh][1][r] = hsum2(a1);
        psm[kh][2][r] = hsum2(a2);
        psm[kh][3][r] = hsum2(a3);
        __syncthreads();

        if (tid < 256) {
            float gi = psm[0][eb][eu]       + psm[1][eb][eu]       + xpf[0];
            float gf = psm[0][eb][eu + 64]  + psm[1][eb][eu + 64]  + xpf[1];
            float gg = psm[0][eb][eu + 128] + psm[1][eb][eu + 128] + xpf[2];
            float go = psm[0][eb][eu + 192] + psm[1][eb][eu + 192] + xpf[3];
            creg = sigf(gf) * creg + sigf(gi) * tanhfast(gg);
            hreg = sigf(go) * tanhfast(creg);

            const int nb   = buf ^ 1;
            const int hoff = (nb * 4 + eb) * 128 + u0 + eu;
            ((float*)hsm)[hoff] = hreg;                       // local copy
            asm volatile("st.shared::cluster.f32 [%0], %1;"   // peer copy (DSMEM)
                         :: "r"(hs_peer + (unsigned)hoff * 4), "f"(hreg) : "memory");

            if (LAYER == 0)
                g_h0[((size_t)(b0 + eb) * Tn + tcur) * 256 + dir * 128 + u0 + eu] = hreg;

            if (s + 1 < Tn) {   // prefetch next xp (consumed next step)
                const int tn2 = tcur + tstep;
                const float* xb = g_xp + ((size_t)(dir * Tn + tn2) * Bn + b0 + eb) * 512 + u0 + eu;
#pragma unroll
                for (int g = 0; g < 4; g++) xpf[g] = xb[g << 7];
            }
        }
        __syncthreads();   // h stores issued; psm consumed; cumulativity for release
        if (tid == 0) {
            asm volatile("mbarrier.arrive.release.cluster.shared::cluster.b64 _, [%0];"
                         :: "r"(mb_self) : "memory");
            asm volatile("mbarrier.arrive.release.cluster.shared::cluster.b64 _, [%0];"
                         :: "r"(mb_peer) : "memory");
        }
        {
            unsigned ph = (unsigned)(s & 1);
            asm volatile(
                "{.reg .pred P;\n\tW1%=: mbarrier.try_wait.parity.acquire.cluster.shared::cta.b64 P,[%0],%1;\n\t"
                "@P bra W2%=;\n\tbra W1%=;\n\tW2%=:}"
                :: "r"(mb_l), "r"(ph) : "memory");
        }

        buf ^= 1;
        tcur += tstep;
    }

    if (LAYER == 1 && tid < 256)
        g_hfin[(dir * Bn + b0 + eb) * 128 + u0 + eu] = hreg;
}

// ---------------------------------------------------------------------------
__global__ void fc_kernel(const float* __restrict__ fcw,
                          const float* __restrict__ fcb,
                          float* __restrict__ out)
{
    int tid = threadIdx.x;  // 256 = 128 b x 2 c
    int b = tid >> 1, c = tid & 1;
    const float* hf = &g_hfin[b * 128];
    const float* hr = &g_hfin[(Bn + b) * 128];
    const float* w  = &fcw[c * 256];
    float s = fcb[c];
#pragma unroll 8
    for (int j = 0; j < 128; j++) s += hf[j] * w[j];
#pragma unroll 8
    for (int j = 0; j < 128; j++) s += hr[j] * w[128 + j];
    out[b * 2 + c] = s;
}

// ---------------------------------------------------------------------------
extern "C" void kernel_launch(void* const* d_in, const int* in_sizes, int n_in,
                              void* d_out, int out_size)
{
    (void)in_sizes; (void)n_in; (void)out_size;
    const int*   x     = (const int*)  d_in[0];
    const float* emb   = (const float*)d_in[1];
    const float* wih0  = (const float*)d_in[2];
    const float* whh0  = (const float*)d_in[3];
    const float* bih0  = (const float*)d_in[4];
    const float* bhh0  = (const float*)d_in[5];
    const float* wih0r = (const float*)d_in[6];
    const float* whh0r = (const float*)d_in[7];
    const float* bih0r = (const float*)d_in[8];
    const float* bhh0r = (const float*)d_in[9];
    const float* wih1  = (const float*)d_in[10];
    const float* whh1  = (const float*)d_in[11];
    const float* bih1  = (const float*)d_in[12];
    const float* bhh1  = (const float*)d_in[13];
    const float* wih1r = (const float*)d_in[14];
    const float* whh1r = (const float*)d_in[15];
    const float* bih1r = (const float*)d_in[16];
    const float* bhh1r = (const float*)d_in[17];
    const float* fcw   = (const float*)d_in[18];
    const float* fcb   = (const float*)d_in[19];
    float* out = (float*)d_out;

    dim3 blk(256);
    dim3 gp(Bn * Tn / 64, 4, 2);

    proj_kernel<100, 20, true><<<gp, blk>>>(x, emb, wih0, wih0r,
                                            bih0, bhh0, bih0r, bhh0r);
    rec_kernel<0><<<128, 512>>>(whh0, whh0r);

    proj_kernel<256, 32, false><<<gp, blk>>>(x, emb, wih1, wih1r,
                                             bih1, bhh1, bih1r, bhh1r);
    rec_kernel<1><<<128, 512>>>(whh1, whh1r);

    fc_kernel<<<1, 256>>>(fcw, fcb, out);
}

// round 14
// speedup vs baseline: 1.2217x; 1.2217x over previous
#include <cuda_runtime.h>
#include <cuda_bf16.h>
#include <cstdint>
#include <cstddef>

#define Bn 128
#define Tn 1024
typedef unsigned long long ull;

__device__ float g_xp[(size_t)2 * Tn * Bn * 512];   // [dir][t][b][512row]
__device__ float g_h0[(size_t)Bn * Tn * 256];       // [b][t][dir*128+u]
__device__ float g_hfin[2 * Bn * 128];              // [dir][b][u]

__device__ __forceinline__ void fma2(ull& d, ull a, ull b) {
    asm("fma.rn.f32x2 %0,%1,%2,%0;" : "+l"(d) : "l"(a), "l"(b));
}
__device__ __forceinline__ float hsum2(ull v) {
    float a, b; asm("mov.b64 {%0,%1},%2;" : "=f"(a), "=f"(b) : "l"(v)); return a + b;
}
__device__ __forceinline__ float sigf(float x) { return __fdividef(1.f, 1.f + __expf(-x)); }
__device__ __forceinline__ float tanhfast(float x) {
    return __fdividef(2.f, 1.f + __expf(-2.f * x)) - 1.f;
}
__device__ __forceinline__ unsigned s2u(const void* p) {
    unsigned a;
    asm("{.reg .u64 t; cvta.to.shared.u64 t, %1; cvt.u32.u64 %0, t;}" : "=r"(a) : "l"(p));
    return a;
}
__device__ __forceinline__ void cp16(void* s, const void* g) {
    asm volatile("cp.async.ca.shared.global [%0], [%1], 16;"
                 :: "r"(s2u(s)), "l"(g) : "memory");
}

// ---------------------------------------------------------------------------
// Projection: g_xp[dir][t][b][row] = A[tok]·W[row] + b_ih + b_hh
// CTA 128 tok x 128 rows, 512 threads, thread = 8 tok x 4 rows.
// A in smem k-transposed as float2 pairs (warp-broadcast loads, direct f32x2
// operands); W rows 32-float pitch, 16B-granule XOR swizzle by (row>>2)&7.
// W filled via cp.async 16B; A via prefetched LDG float4 -> STS. Double-buffered.
// grid: (8, 1024): x = rowtile*2+dir (fast, L2 reuse of A), y = token tile.
// FIX vs R10: ldW uses (rowBase + row) — R10 read tile-0 weights for all tiles.
// ---------------------------------------------------------------------------
template <int K, int CH, bool GATHER>
__global__ void __launch_bounds__(512) proj_kernel(
    const int* __restrict__ x, const float* __restrict__ emb,
    const float* __restrict__ Wf, const float* __restrict__ Wr,
    const float* __restrict__ bif, const float* __restrict__ bhf,
    const float* __restrict__ bir, const float* __restrict__ bhr)
{
    const int rowBase = (blockIdx.x >> 1) * 128;
    const int dir     = blockIdx.x & 1;
    const int tokBase = blockIdx.y * 128;
    const float* __restrict__ W  = dir ? Wr  : Wf;
    const float* __restrict__ bi = dir ? bir : bif;
    const float* __restrict__ bh = dir ? bhr : bhf;

    constexpr int KP  = CH / 2;           // float2 pairs per chunk
    constexpr int KG  = CH / 4;           // 16B granules per chunk
    constexpr int NC  = K / CH;
    constexpr int NA  = 128 * KG;
    constexpr int NW  = 128 * KG;

    extern __shared__ __align__(16) char dsm[];
    float2* AsT2 = (float2*)dsm;                               // [2*KP][128]
    float*  Wsm  = (float*)(dsm + (size_t)2 * KP * 128 * 8);   // [2][128*32]
    int*    xs   = (int*)(Wsm + 2 * 128 * 32);                 // [128]

    const int tid = threadIdx.x;
    const int rg  = tid & 31;   // row group (lane): rows rg*4..+3
    const int tg  = tid >> 5;   // token group (warp): toks tg*8..+7

    if (GATHER && tid < 128) xs[tid] = x[tokBase + tid];
    __syncthreads();

    auto ldW = [&](int c, int b) {
#pragma unroll
        for (int i = 0; i < (NW + 511) / 512; i++) {
            int p = tid + 512 * i;
            if (p < NW) {
                int row = p / KG, g = p - row * KG;
                int gp = g ^ ((row >> 2) & 7);
                cp16(&Wsm[b * 4096 + row * 32 + 4 * gp],
                     W + (size_t)(rowBase + row) * K + c * CH + 4 * g);
            }
        }
        asm volatile("cp.async.commit_group;" ::: "memory");
    };
    auto ldA = [&](int c, float4* ar) {
#pragma unroll
        for (int i = 0; i < (NA + 511) / 512; i++) {
            int p = tid + 512 * i;
            if (p < NA) {
                int tok = p & 127, gq = p >> 7;
                const float* s = GATHER ? emb + (size_t)xs[tok] * K
                                        : g_h0 + (size_t)(tokBase + tok) * 256;
                ar[i] = *(const float4*)(s + c * CH + 4 * gq);
            }
        }
    };
    auto stA = [&](int b, const float4* ar) {
#pragma unroll
        for (int i = 0; i < (NA + 511) / 512; i++) {
            int p = tid + 512 * i;
            if (p < NA) {
                int tok = p & 127, gq = p >> 7;
                AsT2[(b * KP + 2 * gq) * 128 + tok]     = make_float2(ar[i].x, ar[i].y);
                AsT2[(b * KP + 2 * gq + 1) * 128 + tok] = make_float2(ar[i].z, ar[i].w);
            }
        }
    };

    ull acc[8][4];
#pragma unroll
    for (int i = 0; i < 8; i++)
#pragma unroll
        for (int j = 0; j < 4; j++) acc[i][j] = 0ull;

    {
        float4 ar[(NA + 511) / 512];
        ldW(0, 0);
        ldA(0, ar);
        stA(0, ar);
    }
    asm volatile("cp.async.wait_group 0;" ::: "memory");
    __syncthreads();

    for (int c = 0; c < NC; c++) {
        const int b = c & 1;
        float4 ar[(NA + 511) / 512];
        if (c + 1 < NC) { ldW(c + 1, b ^ 1); ldA(c + 1, ar); }
#pragma unroll
        for (int kq = 0; kq < KG; kq++) {
            ulonglong2 wv[4];
            const int gp = kq ^ (rg & 7);
#pragma unroll
            for (int j = 0; j < 4; j++)
                wv[j] = *(const ulonglong2*)&Wsm[b * 4096 + (rg * 4 + j) * 32 + 4 * gp];
            const ulonglong2* ap0 = (const ulonglong2*)&AsT2[(b * KP + 2 * kq) * 128 + tg * 8];
            const ulonglong2* ap1 = (const ulonglong2*)&AsT2[(b * KP + 2 * kq + 1) * 128 + tg * 8];
#pragma unroll
            for (int m = 0; m < 4; m++) {
                ulonglong2 a0 = ap0[m], a1 = ap1[m];
#pragma unroll
                for (int j = 0; j < 4; j++) {
                    fma2(acc[2 * m][j],     a0.x, wv[j].x);
                    fma2(acc[2 * m + 1][j], a0.y, wv[j].x);
                    fma2(acc[2 * m][j],     a1.x, wv[j].y);
                    fma2(acc[2 * m + 1][j], a1.y, wv[j].y);
                }
            }
        }
        if (c + 1 < NC) {
            stA(b ^ 1, ar);
            asm volatile("cp.async.wait_group 0;" ::: "memory");
        }
        __syncthreads();
    }

    float bias[4];
#pragma unroll
    for (int j = 0; j < 4; j++) {
        int row = rowBase + rg * 4 + j;
        bias[j] = bi[row] + bh[row];
    }
#pragma unroll
    for (int i = 0; i < 8; i++) {
        int tok = tokBase + tg * 8 + i;
        int b = tok >> 10, t = tok & 1023;
        float4 o4;
        o4.x = hsum2(acc[i][0]) + bias[0];
        o4.y = hsum2(acc[i][1]) + bias[1];
        o4.z = hsum2(acc[i][2]) + bias[2];
        o4.w = hsum2(acc[i][3]) + bias[3];
        *(float4*)&g_xp[((size_t)(dir * Tn + t) * Bn + b) * 512 + rowBase + rg * 4] = o4;
    }
}

// ---------------------------------------------------------------------------
// Recurrence: 2-CTA cluster per (dir, 4-batch group), 512 threads, k-split.
// Thread = (row slot r in [0,256), k-half kh): 32 w-pairs in regs.
// SKIP-WAIT: warps with kh==rank read only locally-produced h (their k-slice
// equals this CTA's unit half), so they skip the mbarrier wait and start the
// next matvec early; kh!=rank warps wait, and the post-matvec __syncthreads
// keeps every cross-step write hazard ordered behind the phase handshake.
// ---------------------------------------------------------------------------
template <int LAYER>
__global__ void __launch_bounds__(512, 1) __cluster_dims__(2, 1, 1)
rec_kernel(const float* __restrict__ Whf, const float* __restrict__ Whr)
{
    const int rank = (int)(blockIdx.x & 1);
    const int cid  = (int)(blockIdx.x >> 1);
    const int dir  = cid >> 5;
    const int b0   = (cid & 31) * 4;
    const int u0   = rank * 64;
    const int tid  = threadIdx.x;
    const int kh   = tid >> 8;          // k-half (warp-uniform)
    const int r    = tid & 255;         // row slot = unit + gate*64
    const int unit = r & 63;
    const int gate = r >> 6;
    const int wrow = u0 + unit + (gate << 7);   // gate order i,f,g,o
    const float* __restrict__ Wh = dir ? Whr : Whf;

    __shared__ __align__(16) float hsm[2][4][128];
    __shared__ __align__(16) float psm[2][4][256];
    __shared__ __align__(8)  ull   mbar[1];

    ull wp[32];
    {
        const ull* wrp = (const ull*)(Wh + (size_t)wrow * 128 + kh * 64);
#pragma unroll
        for (int kp = 0; kp < 32; kp++) wp[kp] = wrp[kp];
    }

    ((float*)hsm)[tid] = 0.f;   // zero buffer 0 (512 floats, one per thread)
    const unsigned mb_l = s2u(mbar);
    if (tid == 0)
        asm volatile("mbarrier.init.shared.b64 [%0], 2;" :: "r"(mb_l) : "memory");

    unsigned hs_peer, mb_self, mb_peer;
    {
        const unsigned hl = s2u(&hsm[0][0][0]);
        asm("mapa.shared::cluster.u32 %0, %1, %2;" : "=r"(hs_peer) : "r"(hl), "r"((unsigned)(rank ^ 1)));
        asm("mapa.shared::cluster.u32 %0, %1, %2;" : "=r"(mb_self) : "r"(mb_l), "r"((unsigned)rank));
        asm("mapa.shared::cluster.u32 %0, %1, %2;" : "=r"(mb_peer) : "r"(mb_l), "r"((unsigned)(rank ^ 1)));
    }
    asm volatile("barrier.cluster.arrive.aligned;" ::: "memory");
    asm volatile("barrier.cluster.wait.aligned;"   ::: "memory");

    const int tstep = dir ? -1 : 1;
    int tcur = dir ? (Tn - 1) : 0;

    const int eb = tid >> 6;    // elementwise owner (tid<256): batch
    const int eu = tid & 63;    //                              local unit
    float xpf[4];
    if (tid < 256) {
        const float* xb = g_xp + ((size_t)(dir * Tn + tcur) * Bn + b0 + eb) * 512 + u0 + eu;
#pragma unroll
        for (int g = 0; g < 4; g++) xpf[g] = xb[g << 7];
    }

    float creg = 0.f, hreg = 0.f;
    int buf = 0;

    for (int s = 0; s < Tn; s++) {
        ull a0 = 0, a1 = 0, a2 = 0, a3 = 0;
        const float* hb = &hsm[buf][0][kh * 64];
#pragma unroll
        for (int kq = 0; kq < 16; kq++) {
            ulonglong2 v0 = *(const ulonglong2*)&hb[4 * kq];
            ulonglong2 v1 = *(const ulonglong2*)&hb[128 + 4 * kq];
            ulonglong2 v2 = *(const ulonglong2*)&hb[256 + 4 * kq];
            ulonglong2 v3 = *(const ulonglong2*)&hb[384 + 4 * kq];
            fma2(a0, wp[2 * kq], v0.x); fma2(a0, wp[2 * kq + 1], v0.y);
            fma2(a1, wp[2 * kq], v1.x); fma2(a1, wp[2 * kq + 1], v1.y);
            fma2(a2, wp[2 * kq], v2.x); fma2(a2, wp[2 * kq + 1], v2.y);
            fma2(a3, wp[2 * kq], v3.x); fma2(a3, wp[2 * kq + 1], v3.y);
        }
        psm[kh][0][r] = hsum2(a0);
        psm[kh][1][r] = hsum2(a1);
        psm[kh][2][r] = hsum2(a2);
        psm[kh][3][r] = hsum2(a3);
        __syncthreads();

        if (tid < 256) {
            float gi = psm[0][eb][eu]       + psm[1][eb][eu]       + xpf[0];
            float gf = psm[0][eb][eu + 64]  + psm[1][eb][eu + 64]  + xpf[1];
            float gg = psm[0][eb][eu + 128] + psm[1][eb][eu + 128] + xpf[2];
            float go = psm[0][eb][eu + 192] + psm[1][eb][eu + 192] + xpf[3];
            creg = sigf(gf) * creg + sigf(gi) * tanhfast(gg);
            hreg = sigf(go) * tanhfast(creg);

            const int nb   = buf ^ 1;
            const int hoff = (nb * 4 + eb) * 128 + u0 + eu;
            ((float*)hsm)[hoff] = hreg;                       // local copy
            asm volatile("st.shared::cluster.f32 [%0], %1;"   // peer copy (DSMEM)
                         :: "r"(hs_peer + (unsigned)hoff * 4), "f"(hreg) : "memory");

            if (LAYER == 0)
                g_h0[((size_t)(b0 + eb) * Tn + tcur) * 256 + dir * 128 + u0 + eu] = hreg;

            if (s + 1 < Tn) {   // prefetch next xp (consumed next step)
                const int tn2 = tcur + tstep;
                const float* xb = g_xp + ((size_t)(dir * Tn + tn2) * Bn + b0 + eb) * 512 + u0 + eu;
#pragma unroll
                for (int g = 0; g < 4; g++) xpf[g] = xb[g << 7];
            }
        }
        __syncthreads();   // h stores issued; psm consumed; cumulativity for release
        if (tid == 0) {
            asm volatile("mbarrier.arrive.release.cluster.shared::cluster.b64 _, [%0];"
                         :: "r"(mb_self) : "memory");
            asm volatile("mbarrier.arrive.release.cluster.shared::cluster.b64 _, [%0];"
                         :: "r"(mb_peer) : "memory");
        }
        if (kh != rank) {   // only peer-half consumers wait (warp-uniform branch)
            unsigned ph = (unsigned)(s & 1);
            asm volatile(
                "{.reg .pred P;\n\tW1%=: mbarrier.try_wait.parity.acquire.cluster.shared::cta.b64 P,[%0],%1;\n\t"
                "@P bra W2%=;\n\tbra W1%=;\n\tW2%=:}"
                :: "r"(mb_l), "r"(ph) : "memory");
        }

        buf ^= 1;
        tcur += tstep;
    }

    if (LAYER == 1 && tid < 256)
        g_hfin[(dir * Bn + b0 + eb) * 128 + u0 + eu] = hreg;
}

// ---------------------------------------------------------------------------
__global__ void fc_kernel(const float* __restrict__ fcw,
                          const float* __restrict__ fcb,
                          float* __restrict__ out)
{
    int tid = threadIdx.x;  // 256 = 128 b x 2 c
    int b = tid >> 1, c = tid & 1;
    const float* hf = &g_hfin[b * 128];
    const float* hr = &g_hfin[(Bn + b) * 128];
    const float* w  = &fcw[c * 256];
    float s = fcb[c];
#pragma unroll 8
    for (int j = 0; j < 128; j++) s += hf[j] * w[j];
#pragma unroll 8
    for (int j = 0; j < 128; j++) s += hr[j] * w[128 + j];
    out[b * 2 + c] = s;
}

// ---------------------------------------------------------------------------
extern "C" void kernel_launch(void* const* d_in, const int* in_sizes, int n_in,
                              void* d_out, int out_size)
{
    (void)in_sizes; (void)n_in; (void)out_size;
    const int*   x     = (const int*)  d_in[0];
    const float* emb   = (const float*)d_in[1];
    const float* wih0  = (const float*)d_in[2];
    const float* whh0  = (const float*)d_in[3];
    const float* bih0  = (const float*)d_in[4];
    const float* bhh0  = (const float*)d_in[5];
    const float* wih0r = (const float*)d_in[6];
    const float* whh0r = (const float*)d_in[7];
    const float* bih0r = (const float*)d_in[8];
    const float* bhh0r = (const float*)d_in[9];
    const float* wih1  = (const float*)d_in[10];
    const float* whh1  = (const float*)d_in[11];
    const float* bih1  = (const float*)d_in[12];
    const float* bhh1  = (const float*)d_in[13];
    const float* wih1r = (const float*)d_in[14];
    const float* whh1r = (const float*)d_in[15];
    const float* bih1r = (const float*)d_in[16];
    const float* bhh1r = (const float*)d_in[17];
    const float* fcw   = (const float*)d_in[18];
    const float* fcb   = (const float*)d_in[19];
    float* out = (float*)d_out;

    // dynamic smem: A(float2[2*KP][128]) + W(2*128*32 floats) + xs(128 ints)
    const int SM0 = 2 * 10 * 128 * 8 + 2 * 128 * 32 * 4 + 512;  // 53760 (K=100)
    const int SM1 = 2 * 16 * 128 * 8 + 2 * 128 * 32 * 4 + 512;  // 66048 (K=256)
    cudaFuncSetAttribute(proj_kernel<100, 20, true>,
                         cudaFuncAttributeMaxDynamicSharedMemorySize, SM0);
    cudaFuncSetAttribute(proj_kernel<256, 32, false>,
                         cudaFuncAttributeMaxDynamicSharedMemorySize, SM1);

    dim3 gp(8, 1024);   // x = rowtile*2 + dir (fast -> L2 reuse), y = token tile

    proj_kernel<100, 20, true><<<gp, 512, SM0>>>(x, emb, wih0, wih0r,
                                                 bih0, bhh0, bih0r, bhh0r);
    rec_kernel<0><<<128, 512>>>(whh0, whh0r);

    proj_kernel<256, 32, false><<<gp, 512, SM1>>>(x, emb, wih1, wih1r,
                                                  bih1, bhh1, bih1r, bhh1r);
    rec_kernel<1><<<128, 512>>>(whh1, whh1r);

    fc_kernel<<<1, 256>>>(fcw, fcb, out);
}

// round 15
// speedup vs baseline: 1.2673x; 1.0374x over previous
#include <cuda_runtime.h>
#include <cuda_bf16.h>
#include <cstdint>
#include <cstddef>

#define Bn 128
#define Tn 1024
typedef unsigned long long ull;

__device__ float g_xp[(size_t)2 * Tn * Bn * 512];   // [dir][t][b][512row]
__device__ float g_h0[(size_t)Bn * Tn * 256];       // [b][t][dir*128+u]
__device__ float g_hfin[2 * Bn * 128];              // [dir][b][u]

__device__ __forceinline__ void fma2(ull& d, ull a, ull b) {
    asm("fma.rn.f32x2 %0,%1,%2,%0;" : "+l"(d) : "l"(a), "l"(b));
}
__device__ __forceinline__ float hsum2(ull v) {
    float a, b; asm("mov.b64 {%0,%1},%2;" : "=f"(a), "=f"(b) : "l"(v)); return a + b;
}
__device__ __forceinline__ float sigf(float x) { return __fdividef(1.f, 1.f + __expf(-x)); }
__device__ __forceinline__ float tanhfast(float x) {
    return __fdividef(2.f, 1.f + __expf(-2.f * x)) - 1.f;
}
__device__ __forceinline__ unsigned s2u(const void* p) {
    unsigned a;
    asm("{.reg .u64 t; cvta.to.shared.u64 t, %1; cvt.u32.u64 %0, t;}" : "=r"(a) : "l"(p));
    return a;
}
__device__ __forceinline__ void cp16(void* s, const void* g) {
    asm volatile("cp.async.ca.shared.global [%0], [%1], 16;"
                 :: "r"(s2u(s)), "l"(g) : "memory");
}

// ---------------------------------------------------------------------------
// Projection (R14-proven, unchanged): g_xp[dir][t][b][row] = A[tok]·W[row]+bias
// ---------------------------------------------------------------------------
template <int K, int CH, bool GATHER>
__global__ void __launch_bounds__(512) proj_kernel(
    const int* __restrict__ x, const float* __restrict__ emb,
    const float* __restrict__ Wf, const float* __restrict__ Wr,
    const float* __restrict__ bif, const float* __restrict__ bhf,
    const float* __restrict__ bir, const float* __restrict__ bhr)
{
    const int rowBase = (blockIdx.x >> 1) * 128;
    const int dir     = blockIdx.x & 1;
    const int tokBase = blockIdx.y * 128;
    const float* __restrict__ W  = dir ? Wr  : Wf;
    const float* __restrict__ bi = dir ? bir : bif;
    const float* __restrict__ bh = dir ? bhr : bhf;

    constexpr int KP  = CH / 2;
    constexpr int KG  = CH / 4;
    constexpr int NC  = K / CH;
    constexpr int NA  = 128 * KG;
    constexpr int NW  = 128 * KG;

    extern __shared__ __align__(16) char dsm[];
    float2* AsT2 = (float2*)dsm;                               // [2*KP][128]
    float*  Wsm  = (float*)(dsm + (size_t)2 * KP * 128 * 8);   // [2][128*32]
    int*    xs   = (int*)(Wsm + 2 * 128 * 32);                 // [128]

    const int tid = threadIdx.x;
    const int rg  = tid & 31;
    const int tg  = tid >> 5;

    if (GATHER && tid < 128) xs[tid] = x[tokBase + tid];
    __syncthreads();

    auto ldW = [&](int c, int b) {
#pragma unroll
        for (int i = 0; i < (NW + 511) / 512; i++) {
            int p = tid + 512 * i;
            if (p < NW) {
                int row = p / KG, g = p - row * KG;
                int gp = g ^ ((row >> 2) & 7);
                cp16(&Wsm[b * 4096 + row * 32 + 4 * gp],
                     W + (size_t)(rowBase + row) * K + c * CH + 4 * g);
            }
        }
        asm volatile("cp.async.commit_group;" ::: "memory");
    };
    auto ldA = [&](int c, float4* ar) {
#pragma unroll
        for (int i = 0; i < (NA + 511) / 512; i++) {
            int p = tid + 512 * i;
            if (p < NA) {
                int tok = p & 127, gq = p >> 7;
                const float* s = GATHER ? emb + (size_t)xs[tok] * K
                                        : g_h0 + (size_t)(tokBase + tok) * 256;
                ar[i] = *(const float4*)(s + c * CH + 4 * gq);
            }
        }
    };
    auto stA = [&](int b, const float4* ar) {
#pragma unroll
        for (int i = 0; i < (NA + 511) / 512; i++) {
            int p = tid + 512 * i;
            if (p < NA) {
                int tok = p & 127, gq = p >> 7;
                AsT2[(b * KP + 2 * gq) * 128 + tok]     = make_float2(ar[i].x, ar[i].y);
                AsT2[(b * KP + 2 * gq + 1) * 128 + tok] = make_float2(ar[i].z, ar[i].w);
            }
        }
    };

    ull acc[8][4];
#pragma unroll
    for (int i = 0; i < 8; i++)
#pragma unroll
        for (int j = 0; j < 4; j++) acc[i][j] = 0ull;

    {
        float4 ar[(NA + 511) / 512];
        ldW(0, 0);
        ldA(0, ar);
        stA(0, ar);
    }
    asm volatile("cp.async.wait_group 0;" ::: "memory");
    __syncthreads();

    for (int c = 0; c < NC; c++) {
        const int b = c & 1;
        float4 ar[(NA + 511) / 512];
        if (c + 1 < NC) { ldW(c + 1, b ^ 1); ldA(c + 1, ar); }
#pragma unroll
        for (int kq = 0; kq < KG; kq++) {
            ulonglong2 wv[4];
            const int gp = kq ^ (rg & 7);
#pragma unroll
            for (int j = 0; j < 4; j++)
                wv[j] = *(const ulonglong2*)&Wsm[b * 4096 + (rg * 4 + j) * 32 + 4 * gp];
            const ulonglong2* ap0 = (const ulonglong2*)&AsT2[(b * KP + 2 * kq) * 128 + tg * 8];
            const ulonglong2* ap1 = (const ulonglong2*)&AsT2[(b * KP + 2 * kq + 1) * 128 + tg * 8];
#pragma unroll
            for (int m = 0; m < 4; m++) {
                ulonglong2 a0 = ap0[m], a1 = ap1[m];
#pragma unroll
                for (int j = 0; j < 4; j++) {
                    fma2(acc[2 * m][j],     a0.x, wv[j].x);
                    fma2(acc[2 * m + 1][j], a0.y, wv[j].x);
                    fma2(acc[2 * m][j],     a1.x, wv[j].y);
                    fma2(acc[2 * m + 1][j], a1.y, wv[j].y);
                }
            }
        }
        if (c + 1 < NC) {
            stA(b ^ 1, ar);
            asm volatile("cp.async.wait_group 0;" ::: "memory");
        }
        __syncthreads();
    }

    float bias[4];
#pragma unroll
    for (int j = 0; j < 4; j++) {
        int row = rowBase + rg * 4 + j;
        bias[j] = bi[row] + bh[row];
    }
#pragma unroll
    for (int i = 0; i < 8; i++) {
        int tok = tokBase + tg * 8 + i;
        int b = tok >> 10, t = tok & 1023;
        float4 o4;
        o4.x = hsum2(acc[i][0]) + bias[0];
        o4.y = hsum2(acc[i][1]) + bias[1];
        o4.z = hsum2(acc[i][2]) + bias[2];
        o4.w = hsum2(acc[i][3]) + bias[3];
        *(float4*)&g_xp[((size_t)(dir * Tn + t) * Bn + b) * 512 + rowBase + rg * 4] = o4;
    }
}

// ---------------------------------------------------------------------------
// Recurrence: 2-CTA cluster per (dir, 4-batch group), 256 threads.
// Thread = (unit, k-quarter): ALL 4 gates of its unit in regs (4x16 ull wp)
// -> 4x data reuse per h load: 32 LDS.128/thread (was 64 over 512 thr) cuts
// crossbar traffic 512KB -> 128KB per step (the R14 bottleneck, L1=48%).
// psm[kq][g][b][68]: conflict-free STS (lanes=unit) and LDS (lanes=eu).
// Skip-wait preserved: local k-quarters are {2*rank, 2*rank+1}.
// ---------------------------------------------------------------------------
template <int LAYER>
__global__ void __launch_bounds__(256, 1) __cluster_dims__(2, 1, 1)
rec_kernel(const float* __restrict__ Whf, const float* __restrict__ Whr)
{
    const int rank = (int)(blockIdx.x & 1);
    const int cid  = (int)(blockIdx.x >> 1);
    const int dir  = cid >> 5;
    const int b0   = (cid & 31) * 4;
    const int u0   = rank * 64;
    const int tid  = threadIdx.x;
    const int unit = tid & 63;
    const int kq   = tid >> 6;          // k-quarter 0..3 (uniform per 2 warps)
    const float* __restrict__ Wh = dir ? Whr : Whf;

    __shared__ __align__(16) float hsm[2][4][128];      // [buf][b][k]
    __shared__ __align__(16) float psm[4][4][4][68];    // [kq][g][b][unit+pad]
    __shared__ __align__(8)  ull   mbar[1];

    // Weights: all 4 gates for this unit, k-slice kq*32..+32 (gate order i,f,g,o)
    ull wp[4][16];
#pragma unroll
    for (int g = 0; g < 4; g++) {
        const ull* wrp = (const ull*)(Wh + (size_t)((g << 7) + u0 + unit) * 128 + kq * 32);
#pragma unroll
        for (int kp = 0; kp < 16; kp++) wp[g][kp] = wrp[kp];
    }

    ((float*)hsm)[tid] = 0.f;           // zero buffer 0 (512 floats)
    ((float*)hsm)[tid + 256] = 0.f;
    const unsigned mb_l = s2u(mbar);
    if (tid == 0)
        asm volatile("mbarrier.init.shared.b64 [%0], 2;" :: "r"(mb_l) : "memory");

    unsigned hs_peer, mb_self, mb_peer;
    {
        const unsigned hl = s2u(&hsm[0][0][0]);
        asm("mapa.shared::cluster.u32 %0, %1, %2;" : "=r"(hs_peer) : "r"(hl), "r"((unsigned)(rank ^ 1)));
        asm("mapa.shared::cluster.u32 %0, %1, %2;" : "=r"(mb_self) : "r"(mb_l), "r"((unsigned)rank));
        asm("mapa.shared::cluster.u32 %0, %1, %2;" : "=r"(mb_peer) : "r"(mb_l), "r"((unsigned)(rank ^ 1)));
    }
    asm volatile("barrier.cluster.arrive.aligned;" ::: "memory");
    asm volatile("barrier.cluster.wait.aligned;"   ::: "memory");

    const int tstep = dir ? -1 : 1;
    int tcur = dir ? (Tn - 1) : 0;

    const int eb = kq;      // elementwise owner: batch   (identity remap)
    const int eu = unit;    //                    local unit
    float xpf[4];
    {
        const float* xb = g_xp + ((size_t)(dir * Tn + tcur) * Bn + b0 + eb) * 512 + u0 + eu;
#pragma unroll
        for (int g = 0; g < 4; g++) xpf[g] = xb[g << 7];
    }

    float creg = 0.f, hreg = 0.f;
    int buf = 0;
    const bool mustwait = ((kq >> 1) != rank);   // peer-half k consumers

    for (int s = 0; s < Tn; s++) {
        // Matvec: acc[g][b] over k in [kq*32, kq*32+32)
        ull acc[4][4];
#pragma unroll
        for (int g = 0; g < 4; g++)
#pragma unroll
            for (int b = 0; b < 4; b++) acc[g][b] = 0ull;

        const float* hb = &hsm[buf][0][kq * 32];
#pragma unroll
        for (int j = 0; j < 8; j++) {
            ulonglong2 v0 = *(const ulonglong2*)&hb[4 * j];
            ulonglong2 v1 = *(const ulonglong2*)&hb[128 + 4 * j];
            ulonglong2 v2 = *(const ulonglong2*)&hb[256 + 4 * j];
            ulonglong2 v3 = *(const ulonglong2*)&hb[384 + 4 * j];
#pragma unroll
            for (int g = 0; g < 4; g++) {
                fma2(acc[g][0], wp[g][2 * j], v0.x); fma2(acc[g][0], wp[g][2 * j + 1], v0.y);
                fma2(acc[g][1], wp[g][2 * j], v1.x); fma2(acc[g][1], wp[g][2 * j + 1], v1.y);
                fma2(acc[g][2], wp[g][2 * j], v2.x); fma2(acc[g][2], wp[g][2 * j + 1], v2.y);
                fma2(acc[g][3], wp[g][2 * j], v3.x); fma2(acc[g][3], wp[g][2 * j + 1], v3.y);
            }
        }
#pragma unroll
        for (int g = 0; g < 4; g++)
#pragma unroll
            for (int b = 0; b < 4; b++)
                psm[kq][g][b][unit] = hsum2(acc[g][b]);
        __syncthreads();

        // Elementwise cell for (batch eb, unit eu); c stays in register.
        {
            float gi = psm[0][0][eb][eu] + psm[1][0][eb][eu] + psm[2][0][eb][eu] + psm[3][0][eb][eu] + xpf[0];
            float gf = psm[0][1][eb][eu] + psm[1][1][eb][eu] + psm[2][1][eb][eu] + psm[3][1][eb][eu] + xpf[1];
            float gg = psm[0][2][eb][eu] + psm[1][2][eb][eu] + psm[2][2][eb][eu] + psm[3][2][eb][eu] + xpf[2];
            float go = psm[0][3][eb][eu] + psm[1][3][eb][eu] + psm[2][3][eb][eu] + psm[3][3][eb][eu] + xpf[3];
            creg = sigf(gf) * creg + sigf(gi) * tanhfast(gg);
            hreg = sigf(go) * tanhfast(creg);

            const int nb   = buf ^ 1;
            const int hoff = (nb * 4 + eb) * 128 + u0 + eu;
            ((float*)hsm)[hoff] = hreg;                       // local copy
            asm volatile("st.shared::cluster.f32 [%0], %1;"   // peer copy (DSMEM)
                         :: "r"(hs_peer + (unsigned)hoff * 4), "f"(hreg) : "memory");

            if (LAYER == 0)
                g_h0[((size_t)(b0 + eb) * Tn + tcur) * 256 + dir * 128 + u0 + eu] = hreg;

            if (s + 1 < Tn) {   // prefetch next xp
                const int tn2 = tcur + tstep;
                const float* xb = g_xp + ((size_t)(dir * Tn + tn2) * Bn + b0 + eb) * 512 + u0 + eu;
#pragma unroll
                for (int g = 0; g < 4; g++) xpf[g] = xb[g << 7];
            }
        }
        __syncthreads();   // h stores issued; psm consumed; cumulativity for release
        if (tid == 0) {
            asm volatile("mbarrier.arrive.release.cluster.shared::cluster.b64 _, [%0];"
                         :: "r"(mb_self) : "memory");
            asm volatile("mbarrier.arrive.release.cluster.shared::cluster.b64 _, [%0];"
                         :: "r"(mb_peer) : "memory");
        }
        if (mustwait) {   // only peer-half k consumers wait (warp-uniform)
            unsigned ph = (unsigned)(s & 1);
            asm volatile(
                "{.reg .pred P;\n\tW1%=: mbarrier.try_wait.parity.acquire.cluster.shared::cta.b64 P,[%0],%1;\n\t"
                "@P bra W2%=;\n\tbra W1%=;\n\tW2%=:}"
                :: "r"(mb_l), "r"(ph) : "memory");
        }

        buf ^= 1;
        tcur += tstep;
    }

    if (LAYER == 1)
        g_hfin[(dir * Bn + b0 + eb) * 128 + u0 + eu] = hreg;
}

// ---------------------------------------------------------------------------
__global__ void fc_kernel(const float* __restrict__ fcw,
                          const float* __restrict__ fcb,
                          float* __restrict__ out)
{
    int tid = threadIdx.x;  // 256 = 128 b x 2 c
    int b = tid >> 1, c = tid & 1;
    const float* hf = &g_hfin[b * 128];
    const float* hr = &g_hfin[(Bn + b) * 128];
    const float* w  = &fcw[c * 256];
    float s = fcb[c];
#pragma unroll 8
    for (int j = 0; j < 128; j++) s += hf[j] * w[j];
#pragma unroll 8
    for (int j = 0; j < 128; j++) s += hr[j] * w[128 + j];
    out[b * 2 + c] = s;
}

// ---------------------------------------------------------------------------
extern "C" void kernel_launch(void* const* d_in, const int* in_sizes, int n_in,
                              void* d_out, int out_size)
{
    (void)in_sizes; (void)n_in; (void)out_size;
    const int*   x     = (const int*)  d_in[0];
    const float* emb   = (const float*)d_in[1];
    const float* wih0  = (const float*)d_in[2];
    const float* whh0  = (const float*)d_in[3];
    const float* bih0  = (const float*)d_in[4];
    const float* bhh0  = (const float*)d_in[5];
    const float* wih0r = (const float*)d_in[6];
    const float* whh0r = (const float*)d_in[7];
    const float* bih0r = (const float*)d_in[8];
    const float* bhh0r = (const float*)d_in[9];
    const float* wih1  = (const float*)d_in[10];
    const float* whh1  = (const float*)d_in[11];
    const float* bih1  = (const float*)d_in[12];
    const float* bhh1  = (const float*)d_in[13];
    const float* wih1r = (const float*)d_in[14];
    const float* whh1r = (const float*)d_in[15];
    const float* bih1r = (const float*)d_in[16];
    const float* bhh1r = (const float*)d_in[17];
    const float* fcw   = (const float*)d_in[18];
    const float* fcb   = (const float*)d_in[19];
    float* out = (float*)d_out;

    const int SM0 = 2 * 10 * 128 * 8 + 2 * 128 * 32 * 4 + 512;  // 53760 (K=100)
    const int SM1 = 2 * 16 * 128 * 8 + 2 * 128 * 32 * 4 + 512;  // 66048 (K=256)
    cudaFuncSetAttribute(proj_kernel<100, 20, true>,
                         cudaFuncAttributeMaxDynamicSharedMemorySize, SM0);
    cudaFuncSetAttribute(proj_kernel<256, 32, false>,
                         cudaFuncAttributeMaxDynamicSharedMemorySize, SM1);

    dim3 gp(8, 1024);   // x = rowtile*2 + dir, y = token tile

    proj_kernel<100, 20, true><<<gp, 512, SM0>>>(x, emb, wih0, wih0r,
                                                 bih0, bhh0, bih0r, bhh0r);
    rec_kernel<0><<<128, 256>>>(whh0, whh0r);

    proj_kernel<256, 32, false><<<gp, 512, SM1>>>(x, emb, wih1, wih1r,
                                                  bih1, bhh1, bih1r, bhh1r);
    rec_kernel<1><<<128, 256>>>(whh1, whh1r);

    fc_kernel<<<1, 256>>>(fcw, fcb, out);
}

// round 17
// speedup vs baseline: 1.3865x; 1.0940x over previous
#include <cuda_runtime.h>
#include <cuda_bf16.h>
#include <cstdint>
#include <cstddef>

#define Bn 128
#define Tn 1024
#define Vn 50000
#define Vpad 50048
typedef unsigned long long ull;

__device__ float g_xp[(size_t)2 * Tn * Bn * 512];   // [dir][t][b][512row] (layer1 only)
__device__ float g_h0[(size_t)Bn * Tn * 256];       // [b][t][dir*128+u]
__device__ float g_tab[(size_t)Vpad * 1024];        // [v][dir*512+row]  vocab-projected
__device__ float g_hfin[2 * Bn * 128];              // [dir][b][u]

__device__ __forceinline__ void fma2(ull& d, ull a, ull b) {
    asm("fma.rn.f32x2 %0,%1,%2,%0;" : "+l"(d) : "l"(a), "l"(b));
}
__device__ __forceinline__ float hsum2(ull v) {
    float a, b; asm("mov.b64 {%0,%1},%2;" : "=f"(a), "=f"(b) : "l"(v)); return a + b;
}
__device__ __forceinline__ float sigf(float x) { return __fdividef(1.f, 1.f + __expf(-x)); }
__device__ __forceinline__ float tanhfast(float x) {
    return __fdividef(2.f, 1.f + __expf(-2.f * x)) - 1.f;
}
__device__ __forceinline__ unsigned s2u(const void* p) {
    unsigned a;
    asm("{.reg .u64 t; cvta.to.shared.u64 t, %1; cvt.u32.u64 %0, t;}" : "=r"(a) : "l"(p));
    return a;
}
__device__ __forceinline__ void cp16(void* s, const void* g) {
    asm volatile("cp.async.ca.shared.global [%0], [%1], 16;"
                 :: "r"(s2u(s)), "l"(g) : "memory");
}

// ---------------------------------------------------------------------------
// Projection (R15-proven body). OUT=0: g_xp[dir][t][b][row] for real tokens.
// OUT=1: vocab-table mode — "tokens" are vocab ids (clamped at Vn-1; table is
// padded so unguarded writes are safe), output -> g_tab[v][dir*512+row].
// ---------------------------------------------------------------------------
template <int K, int CH, bool GATHER, int OUT>
__global__ void __launch_bounds__(512) proj_kernel(
    const int* __restrict__ x, const float* __restrict__ emb,
    const float* __restrict__ Wf, const float* __restrict__ Wr,
    const float* __restrict__ bif, const float* __restrict__ bhf,
    const float* __restrict__ bir, const float* __restrict__ bhr)
{
    const int rowBase = (blockIdx.x >> 1) * 128;
    const int dir     = blockIdx.x & 1;
    const int tokBase = blockIdx.y * 128;
    const float* __restrict__ W  = dir ? Wr  : Wf;
    const float* __restrict__ bi = dir ? bir : bif;
    const float* __restrict__ bh = dir ? bhr : bhf;

    constexpr int KP  = CH / 2;
    constexpr int KG  = CH / 4;
    constexpr int NC  = K / CH;
    constexpr int NA  = 128 * KG;
    constexpr int NW  = 128 * KG;

    extern __shared__ __align__(16) char dsm[];
    float2* AsT2 = (float2*)dsm;                               // [2*KP][128]
    float*  Wsm  = (float*)(dsm + (size_t)2 * KP * 128 * 8);   // [2][128*32]
    int*    xs   = (int*)(Wsm + 2 * 128 * 32);                 // [128]

    const int tid = threadIdx.x;
    const int rg  = tid & 31;
    const int tg  = tid >> 5;

    if (GATHER && tid < 128)
        xs[tid] = (OUT == 1) ? min(tokBase + tid, Vn - 1) : x[tokBase + tid];
    __syncthreads();

    auto ldW = [&](int c, int b) {
#pragma unroll
        for (int i = 0; i < (NW + 511) / 512; i++) {
            int p = tid + 512 * i;
            if (p < NW) {
                int row = p / KG, g = p - row * KG;
                int gp = g ^ ((row >> 2) & 7);
                cp16(&Wsm[b * 4096 + row * 32 + 4 * gp],
                     W + (size_t)(rowBase + row) * K + c * CH + 4 * g);
            }
        }
        asm volatile("cp.async.commit_group;" ::: "memory");
    };
    auto ldA = [&](int c, float4* ar) {
#pragma unroll
        for (int i = 0; i < (NA + 511) / 512; i++) {
            int p = tid + 512 * i;
            if (p < NA) {
                int tok = p & 127, gq = p >> 7;
                const float* s = GATHER ? emb + (size_t)xs[tok] * K
                                        : g_h0 + (size_t)(tokBase + tok) * 256;
                ar[i] = *(const float4*)(s + c * CH + 4 * gq);
            }
        }
    };
    auto stA = [&](int b, const float4* ar) {
#pragma unroll
        for (int i = 0; i < (NA + 511) / 512; i++) {
            int p = tid + 512 * i;
            if (p < NA) {
                int tok = p & 127, gq = p >> 7;
                AsT2[(b * KP + 2 * gq) * 128 + tok]     = make_float2(ar[i].x, ar[i].y);
                AsT2[(b * KP + 2 * gq + 1) * 128 + tok] = make_float2(ar[i].z, ar[i].w);
            }
        }
    };

    ull acc[8][4];
#pragma unroll
    for (int i = 0; i < 8; i++)
#pragma unroll
        for (int j = 0; j < 4; j++) acc[i][j] = 0ull;

    {
        float4 ar[(NA + 511) / 512];
        ldW(0, 0);
        ldA(0, ar);
        stA(0, ar);
    }
    asm volatile("cp.async.wait_group 0;" ::: "memory");
    __syncthreads();

    for (int c = 0; c < NC; c++) {
        const int b = c & 1;
        float4 ar[(NA + 511) / 512];
        if (c + 1 < NC) { ldW(c + 1, b ^ 1); ldA(c + 1, ar); }
#pragma unroll
        for (int kq = 0; kq < KG; kq++) {
            ulonglong2 wv[4];
            const int gp = kq ^ (rg & 7);
#pragma unroll
            for (int j = 0; j < 4; j++)
                wv[j] = *(const ulonglong2*)&Wsm[b * 4096 + (rg * 4 + j) * 32 + 4 * gp];
            const ulonglong2* ap0 = (const ulonglong2*)&AsT2[(b * KP + 2 * kq) * 128 + tg * 8];
            const ulonglong2* ap1 = (const ulonglong2*)&AsT2[(b * KP + 2 * kq + 1) * 128 + tg * 8];
#pragma unroll
            for (int m = 0; m < 4; m++) {
                ulonglong2 a0 = ap0[m], a1 = ap1[m];
#pragma unroll
                for (int j = 0; j < 4; j++) {
                    fma2(acc[2 * m][j],     a0.x, wv[j].x);
                    fma2(acc[2 * m + 1][j], a0.y, wv[j].x);
                    fma2(acc[2 * m][j],     a1.x, wv[j].y);
                    fma2(acc[2 * m + 1][j], a1.y, wv[j].y);
                }
            }
        }
        if (c + 1 < NC) {
            stA(b ^ 1, ar);
            asm volatile("cp.async.wait_group 0;" ::: "memory");
        }
        __syncthreads();
    }

    float bias[4];
#pragma unroll
    for (int j = 0; j < 4; j++) {
        int row = rowBase + rg * 4 + j;
        bias[j] = bi[row] + bh[row];
    }
#pragma unroll
    for (int i = 0; i < 8; i++) {
        int tok = tokBase + tg * 8 + i;
        float4 o4;
        o4.x = hsum2(acc[i][0]) + bias[0];
        o4.y = hsum2(acc[i][1]) + bias[1];
        o4.z = hsum2(acc[i][2]) + bias[2];
        o4.w = hsum2(acc[i][3]) + bias[3];
        if (OUT == 0) {
            int b = tok >> 10, t = tok & 1023;
            *(float4*)&g_xp[((size_t)(dir * Tn + t) * Bn + b) * 512 + rowBase + rg * 4] = o4;
        } else {
            *(float4*)&g_tab[(size_t)tok * 1024 + dir * 512 + rowBase + rg * 4] = o4;
        }
    }
}

// ---------------------------------------------------------------------------
// Recurrence (R15-proven): 2-CTA cluster, 256 threads, 4-gate reuse.
// LAYER0: xp read from g_tab via x[b][t] indirection (vocab factoring) —
// same 4 LDGs per thread per step as the old g_xp read, prefetched 1 step.
// LAYER1: xp from g_xp (unchanged).
// ---------------------------------------------------------------------------
template <int LAYER>
__global__ void __launch_bounds__(256, 1) __cluster_dims__(2, 1, 1)
rec_kernel(const float* __restrict__ Whf, const float* __restrict__ Whr,
           const int* __restrict__ xx)
{
    const int rank = (int)(blockIdx.x & 1);
    const int cid  = (int)(blockIdx.x >> 1);
    const int dir  = cid >> 5;
    const int b0   = (cid & 31) * 4;
    const int u0   = rank * 64;
    const int tid  = threadIdx.x;
    const int unit = tid & 63;
    const int kq   = tid >> 6;
    const float* __restrict__ Wh = dir ? Whr : Whf;

    __shared__ __align__(16) float hsm[2][4][128];
    __shared__ __align__(16) float psm[4][4][4][68];
    __shared__ __align__(8)  ull   mbar[1];

    ull wp[4][16];
#pragma unroll
    for (int g = 0; g < 4; g++) {
        const ull* wrp = (const ull*)(Wh + (size_t)((g << 7) + u0 + unit) * 128 + kq * 32);
#pragma unroll
        for (int kp = 0; kp < 16; kp++) wp[g][kp] = wrp[kp];
    }

    ((float*)hsm)[tid] = 0.f;
    ((float*)hsm)[tid + 256] = 0.f;
    const unsigned mb_l = s2u(mbar);
    if (tid == 0)
        asm volatile("mbarrier.init.shared.b64 [%0], 2;" :: "r"(mb_l) : "memory");

    unsigned hs_peer, mb_self, mb_peer;
    {
        const unsigned hl = s2u(&hsm[0][0][0]);
        asm("mapa.shared::cluster.u32 %0, %1, %2;" : "=r"(hs_peer) : "r"(hl), "r"((unsigned)(rank ^ 1)));
        asm("mapa.shared::cluster.u32 %0, %1, %2;" : "=r"(mb_self) : "r"(mb_l), "r"((unsigned)rank));
        asm("mapa.shared::cluster.u32 %0, %1, %2;" : "=r"(mb_peer) : "r"(mb_l), "r"((unsigned)(rank ^ 1)));
    }
    asm volatile("barrier.cluster.arrive.aligned;" ::: "memory");
    asm volatile("barrier.cluster.wait.aligned;"   ::: "memory");

    const int tstep = dir ? -1 : 1;
    int tcur = dir ? (Tn - 1) : 0;

    const int eb = kq;
    const int eu = unit;
    const int* __restrict__ xrow = (LAYER == 0) ? (xx + (size_t)(b0 + eb) * Tn) : nullptr;

    float xpf[4];
    if (LAYER == 0) {
        const float* xb = g_tab + (size_t)xrow[tcur] * 1024 + dir * 512 + u0 + eu;
#pragma unroll
        for (int g = 0; g < 4; g++) xpf[g] = xb[g << 7];
    } else {
        const float* xb = g_xp + ((size_t)(dir * Tn + tcur) * Bn + b0 + eb) * 512 + u0 + eu;
#pragma unroll
        for (int g = 0; g < 4; g++) xpf[g] = xb[g << 7];
    }

    float creg = 0.f, hreg = 0.f;
    int buf = 0;
    const bool mustwait = ((kq >> 1) != rank);

    for (int s = 0; s < Tn; s++) {
        ull acc[4][4];
#pragma unroll
        for (int g = 0; g < 4; g++)
#pragma unroll
            for (int b = 0; b < 4; b++) acc[g][b] = 0ull;

        const float* hb = &hsm[buf][0][kq * 32];
#pragma unroll
        for (int j = 0; j < 8; j++) {
            ulonglong2 v0 = *(const ulonglong2*)&hb[4 * j];
            ulonglong2 v1 = *(const ulonglong2*)&hb[128 + 4 * j];
            ulonglong2 v2 = *(const ulonglong2*)&hb[256 + 4 * j];
            ulonglong2 v3 = *(const ulonglong2*)&hb[384 + 4 * j];
#pragma unroll
            for (int g = 0; g < 4; g++) {
                fma2(acc[g][0], wp[g][2 * j], v0.x); fma2(acc[g][0], wp[g][2 * j + 1], v0.y);
                fma2(acc[g][1], wp[g][2 * j], v1.x); fma2(acc[g][1], wp[g][2 * j + 1], v1.y);
                fma2(acc[g][2], wp[g][2 * j], v2.x); fma2(acc[g][2], wp[g][2 * j + 1], v2.y);
                fma2(acc[g][3], wp[g][2 * j], v3.x); fma2(acc[g][3], wp[g][2 * j + 1], v3.y);
            }
        }
#pragma unroll
        for (int g = 0; g < 4; g++)
#pragma unroll
            for (int b = 0; b < 4; b++)
                psm[kq][g][b][unit] = hsum2(acc[g][b]);
        __syncthreads();

        {
            float gi = psm[0][0][eb][eu] + psm[1][0][eb][eu] + psm[2][0][eb][eu] + psm[3][0][eb][eu] + xpf[0];
            float gf = psm[0][1][eb][eu] + psm[1][1][eb][eu] + psm[2][1][eb][eu] + psm[3][1][eb][eu] + xpf[1];
            float gg = psm[0][2][eb][eu] + psm[1][2][eb][eu] + psm[2][2][eb][eu] + psm[3][2][eb][eu] + xpf[2];
            float go = psm[0][3][eb][eu] + psm[1][3][eb][eu] + psm[2][3][eb][eu] + psm[3][3][eb][eu] + xpf[3];
            creg = sigf(gf) * creg + sigf(gi) * tanhfast(gg);
            hreg = sigf(go) * tanhfast(creg);

            const int nb   = buf ^ 1;
            const int hoff = (nb * 4 + eb) * 128 + u0 + eu;
            ((float*)hsm)[hoff] = hreg;
            asm volatile("st.shared::cluster.f32 [%0], %1;"
                         :: "r"(hs_peer + (unsigned)hoff * 4), "f"(hreg) : "memory");

            if (LAYER == 0)
                g_h0[((size_t)(b0 + eb) * Tn + tcur) * 256 + dir * 128 + u0 + eu] = hreg;

            if (s + 1 < Tn) {
                const int tn2 = tcur + tstep;
                const float* xb = (LAYER == 0)
                    ? g_tab + (size_t)xrow[tn2] * 1024 + dir * 512 + u0 + eu
                    : g_xp + ((size_t)(dir * Tn + tn2) * Bn + b0 + eb) * 512 + u0 + eu;
#pragma unroll
                for (int g = 0; g < 4; g++) xpf[g] = xb[g << 7];
            }
        }
        __syncthreads();
        if (tid == 0) {
            asm volatile("mbarrier.arrive.release.cluster.shared::cluster.b64 _, [%0];"
                         :: "r"(mb_self) : "memory");
            asm volatile("mbarrier.arrive.release.cluster.shared::cluster.b64 _, [%0];"
                         :: "r"(mb_peer) : "memory");
        }
        if (mustwait) {
            unsigned ph = (unsigned)(s & 1);
            asm volatile(
                "{.reg .pred P;\n\tW1%=: mbarrier.try_wait.parity.acquire.cluster.shared::cta.b64 P,[%0],%1;\n\t"
                "@P bra W2%=;\n\tbra W1%=;\n\tW2%=:}"
                :: "r"(mb_l), "r"(ph) : "memory");
        }

        buf ^= 1;
        tcur += tstep;
    }

    if (LAYER == 1)
        g_hfin[(dir * Bn + b0 + eb) * 128 + u0 + eu] = hreg;
}

// ---------------------------------------------------------------------------
__global__ void fc_kernel(const float* __restrict__ fcw,
                          const float* __restrict__ fcb,
                          float* __restrict__ out)
{
    int tid = threadIdx.x;  // 256 = 128 b x 2 c
    int b = tid >> 1, c = tid & 1;
    const float* hf = &g_hfin[b * 128];
    const float* hr = &g_hfin[(Bn + b) * 128];
    const float* w  = &fcw[c * 256];
    float s = fcb[c];
#pragma unroll 8
    for (int j = 0; j < 128; j++) s += hf[j] * w[j];
#pragma unroll 8
    for (int j = 0; j < 128; j++) s += hr[j] * w[128 + j];
    out[b * 2 + c] = s;
}

// ---------------------------------------------------------------------------
extern "C" void kernel_launch(void* const* d_in, const int* in_sizes, int n_in,
                              void* d_out, int out_size)
{
    (void)in_sizes; (void)n_in; (void)out_size;
    const int*   x     = (const int*)  d_in[0];
    const float* emb   = (const float*)d_in[1];
    const float* wih0  = (const float*)d_in[2];
    const float* whh0  = (const float*)d_in[3];
    const float* bih0  = (const float*)d_in[4];
    const float* bhh0  = (const float*)d_in[5];
    const float* wih0r = (const float*)d_in[6];
    const float* whh0r = (const float*)d_in[7];
    const float* bih0r = (const float*)d_in[8];
    const float* bhh0r = (const float*)d_in[9];
    const float* wih1  = (const float*)d_in[10];
    const float* whh1  = (const float*)d_in[11];
    const float* bih1  = (const float*)d_in[12];
    const float* bhh1  = (const float*)d_in[13];
    const float* wih1r = (const float*)d_in[14];
    const float* whh1r = (const float*)d_in[15];
    const float* bih1r = (const float*)d_in[16];
    const float* bhh1r = (const float*)d_in[17];
    const float* fcw   = (const float*)d_in[18];
    const float* fcb   = (const float*)d_in[19];
    float* out = (float*)d_out;

    const int SM0 = 2 * 10 * 128 * 8 + 2 * 128 * 32 * 4 + 512;  // 53760 (K=100)
    const int SM1 = 2 * 16 * 128 * 8 + 2 * 128 * 32 * 4 + 512;  // 66048 (K=256)
    cudaFuncSetAttribute(proj_kernel<100, 20, true, 1>,
                         cudaFuncAttributeMaxDynamicSharedMemorySize, SM0);
    cudaFuncSetAttribute(proj_kernel<256, 32, false, 0>,
                         cudaFuncAttributeMaxDynamicSharedMemorySize, SM1);

    // layer 0: vocab-factored projection (50048 padded vocab rows, K=100)
    proj_kernel<100, 20, true, 1><<<dim3(8, Vpad / 128), 512, SM0>>>(
        x, emb, wih0, wih0r, bih0, bhh0, bih0r, bhh0r);
    rec_kernel<0><<<128, 256>>>(whh0, whh0r, x);

    // layer 1: token projection from g_h0 (K=256) then recurrence
    proj_kernel<256, 32, false, 0><<<dim3(8, 1024), 512, SM1>>>(
        x, emb, wih1, wih1r, bih1, bhh1, bih1r, bhh1r);
    rec_kernel<1><<<128, 256>>>(whh1, whh1r, x);

    fc_kernel<<<1, 256>>>(fcw, fcb, out);
}